// round 8
// baseline (speedup 1.0000x reference)
#include <cuda_runtime.h>

#define FULLMASK 0xffffffffu
#define WSTRIDE 260
#define NT 256
#define JB 2                            // batches per lane (4 groups of 8 lanes)

// ---- smem layout (float offsets) ----
#define OFF_W1T  0                      // [64][260]  Whh1^T (permuted rows)
#define OFF_W2T  (64 * WSTRIDE)         // [128][260] rows 0..63 Wih2^T, 64..127 Whh2^T
#define OFF_WIH1 (OFF_W2T + 128 * WSTRIDE)
#define OFF_CB1  (OFF_WIH1 + 256)
#define OFF_CB2  (OFF_CB1 + 256)
#define OFF_WOUT (OFF_CB2 + 256)        // [2][1664]
#define OFF_XS   (OFF_WOUT + 3328)      // [64][24]
#define SMEM_FLOATS (OFF_XS + 64 * 24)
#define SMEM_BYTES  (SMEM_FLOATS * 4)   // 222208 B

typedef unsigned long long u64;

static __device__ __forceinline__ u64 splat2(float x) {
    u64 d;
    asm("mov.b64 %0, {%1, %1};" : "=l"(d) : "f"(x));
    return d;
}
static __device__ __forceinline__ float2 unpack2(u64 v) {
    float lo, hi;
    asm("mov.b64 {%0, %1}, %2;" : "=f"(lo), "=f"(hi) : "l"(v));
    return make_float2(lo, hi);
}
static __device__ __forceinline__ u64 fma2(u64 a, u64 b, u64 c) {
    u64 d;
    asm("fma.rn.f32x2 %0, %1, %2, %3;" : "=l"(d) : "l"(a), "l"(b), "l"(c));
    return d;
}

// Fused SLSTM pointwise with shared reciprocals: 5 EX2 + 2 RCP.
static __device__ __forceinline__ void cellpw(float Gi, float Gf, float Gg, float Go,
                                              float& syn, float& mem, float& spk,
                                              float thr) {
    float a = 1.0f + __expf(-Gi);
    float c = 1.0f + __expf(-Gf);
    float b = 1.0f + __expf(-2.0f * Gg);
    float ab = a * b;
    float r = __fdividef(1.0f, ab * c);
    float sn = (ab * syn + c * (2.0f - b)) * r;
    float p = 1.0f + __expf(-Go);
    float q = 1.0f + __expf(-2.0f * sn);
    float s = __fdividef(1.0f, p * q);
    float rst = (mem > thr) ? thr : 0.0f;
    float mn = s * (2.0f - q) - rst;
    syn = sn;
    mem = mn;
    spk = (mn > thr) ? 1.0f : 0.0f;
}

// Weight row permutation: within an h-row (256 floats), chunk i = gate*2+half
// holds, for lane p, floats W[h][gate*64 + p*8 + half*4 .. +3] at
// row_off = i*32 + p*4. Each LDS.128 then reads 8 contiguous 128B lane-chunks:
// 1 wavefront, conflict-free, 4-group broadcast dedup.
static __device__ __forceinline__ int wperm(int r) {   // r = gate*64 + neuron
    int gate = r >> 6, neu = r & 63;
    int p = neu >> 3, half = (neu >> 2) & 1, q = neu & 3;
    return ((gate * 2 + half) * 8 + p) * 4 + q;
}

// 64-row matvec. Lane owns 8 neurons (p*8..p*8+7), JB=2 batches.
// src[n][j]: neuron (p*8+n) state for batch j. Neuron h owned by lane
// srcbase + (h>>3), component h&7. acc[g][j][pr]: f32x2 over neurons 2pr,2pr+1.
static __device__ __forceinline__ void gemm64(u64 (&acc)[4][JB][4],
                                              const float* __restrict__ wbase,
                                              const float (&src)[8][JB],
                                              int srcbase, int p4) {
#pragma unroll 1
    for (int hh = 0; hh < 8; ++hh) {
#pragma unroll
        for (int hl = 0; hl < 8; ++hl) {
            const float* wr = wbase + (hh * 8 + hl) * WSTRIDE + p4;
            u64 wv[4][4];
#pragma unroll
            for (int g = 0; g < 4; ++g) {
                ulonglong2 A = *(const ulonglong2*)(wr + (g * 2) * 32);
                ulonglong2 B = *(const ulonglong2*)(wr + (g * 2 + 1) * 32);
                wv[g][0] = A.x; wv[g][1] = A.y; wv[g][2] = B.x; wv[g][3] = B.y;
            }
#pragma unroll
            for (int j = 0; j < JB; ++j) {
                u64 s = splat2(__shfl_sync(FULLMASK, src[hl][j], srcbase + hh));
#pragma unroll
                for (int g = 0; g < 4; ++g)
#pragma unroll
                    for (int pr = 0; pr < 4; ++pr)
                        acc[g][j][pr] = fma2(s, wv[g][pr], acc[g][j][pr]);
            }
        }
    }
}

__global__ void __launch_bounds__(NT, 1)
snn_kernel(const float* __restrict__ x,
           const float* __restrict__ Wih1, const float* __restrict__ Whh1,
           const float* __restrict__ bih1, const float* __restrict__ bhh1,
           const float* __restrict__ thr1p,
           const float* __restrict__ Wih2, const float* __restrict__ Whh2,
           const float* __restrict__ bih2, const float* __restrict__ bhh2,
           const float* __restrict__ thr2p,
           const float* __restrict__ Wout, const float* __restrict__ bout,
           float* __restrict__ out) {
    extern __shared__ float sm[];
    const int tid  = threadIdx.x;
    const int lane = tid & 31;
    const int w    = tid >> 5;
    const int p    = lane & 7;           // position within 8-lane group
    const int grp  = lane >> 3;          // batch group (0..3)
    const int n0   = p << 3;             // this lane's 8 neurons
    const int p4   = p << 2;             // float offset of lane's 16B chunk
    const int srcbase = grp << 3;
    const int bl   = w * 8 + grp * JB;   // local batch base
    const int cta_b0 = blockIdx.x * 64;

    // ---- stage weights (transposed + per-row permuted, stride 260) ----
    for (int i = tid; i < 256 * 64; i += NT) {
        int r = i >> 6, h = i & 63;
        int d = wperm(r);
        sm[OFF_W1T + h * WSTRIDE + d]        = Whh1[i];
        sm[OFF_W2T + h * WSTRIDE + d]        = Wih2[i];
        sm[OFF_W2T + (64 + h) * WSTRIDE + d] = Whh2[i];
    }
    if (tid < 256) {
        sm[OFF_WIH1 + tid] = Wih1[tid];
        sm[OFF_CB1 + tid]  = bih1[tid] + bhh1[tid];
        sm[OFF_CB2 + tid]  = bih2[tid] + bhh2[tid];
    }
    for (int i = tid; i < 3328; i += NT) sm[OFF_WOUT + i] = Wout[i];
    for (int i = tid; i < 64 * 24; i += NT) sm[OFF_XS + i] = x[cta_b0 * 24 + i];
    __syncthreads();

    const float thr1 = thr1p[0], thr2 = thr2p[0];

    // register-resident state: [neuron component 0..7][batch j]
    float syn1[8][JB], mem1[8][JB], syn2[8][JB], mem2[8][JB], spk1[8][JB];
#pragma unroll
    for (int n = 0; n < 8; ++n)
#pragma unroll
        for (int j = 0; j < JB; ++j)
            syn1[n][j] = mem1[n][j] = syn2[n][j] = mem2[n][j] = spk1[n][j] = 0.0f;

    float oa[JB][2];
#pragma unroll
    for (int j = 0; j < JB; ++j) oa[j][0] = oa[j][1] = 0.0f;

    u64 acc[4][JB][4];

#pragma unroll 1
    for (int t = 0; t < 25; ++t) {
        if (t < 24) {
            // ---- layer 1: gates = mem1 @ Whh1^T + x*Wih1 + b ----
#pragma unroll
            for (int g = 0; g < 4; ++g)
#pragma unroll
                for (int j = 0; j < JB; ++j)
#pragma unroll
                    for (int pr = 0; pr < 4; ++pr) acc[g][j][pr] = 0ull;
            gemm64(acc, sm + OFF_W1T, mem1, srcbase, p4);
#pragma unroll
            for (int j = 0; j < JB; ++j) {
                float xv = sm[OFF_XS + (bl + j) * 24 + t];
                float2 G[4][4];
#pragma unroll
                for (int g = 0; g < 4; ++g)
#pragma unroll
                    for (int pr = 0; pr < 4; ++pr) G[g][pr] = unpack2(acc[g][j][pr]);
#pragma unroll
                for (int n = 0; n < 8; ++n) {
                    float Gi = ((n & 1) ? G[0][n >> 1].y : G[0][n >> 1].x)
                             + sm[OFF_CB1 + 0 * 64 + n0 + n]
                             + xv * sm[OFF_WIH1 + 0 * 64 + n0 + n];
                    float Gf = ((n & 1) ? G[1][n >> 1].y : G[1][n >> 1].x)
                             + sm[OFF_CB1 + 1 * 64 + n0 + n]
                             + xv * sm[OFF_WIH1 + 1 * 64 + n0 + n];
                    float Gg = ((n & 1) ? G[2][n >> 1].y : G[2][n >> 1].x)
                             + sm[OFF_CB1 + 2 * 64 + n0 + n]
                             + xv * sm[OFF_WIH1 + 2 * 64 + n0 + n];
                    float Go = ((n & 1) ? G[3][n >> 1].y : G[3][n >> 1].x)
                             + sm[OFF_CB1 + 3 * 64 + n0 + n]
                             + xv * sm[OFF_WIH1 + 3 * 64 + n0 + n];
                    cellpw(Gi, Gf, Gg, Go, syn1[n][j], mem1[n][j], spk1[n][j], thr1);
                }
            }
        }
        // ---- layer 2: input = spk1 (t<24) or mem1 (extra step t==24) ----
#pragma unroll
        for (int g = 0; g < 4; ++g)
#pragma unroll
            for (int j = 0; j < JB; ++j)
#pragma unroll
                for (int pr = 0; pr < 4; ++pr) acc[g][j][pr] = 0ull;
        gemm64(acc, sm + OFF_W2T + 64 * WSTRIDE, mem2, srcbase, p4);
        if (t < 24) gemm64(acc, sm + OFF_W2T, spk1, srcbase, p4);
        else        gemm64(acc, sm + OFF_W2T, mem1, srcbase, p4);

        const int wcol = t * 64;
#pragma unroll
        for (int j = 0; j < JB; ++j) {
            float2 G[4][4];
#pragma unroll
            for (int g = 0; g < 4; ++g)
#pragma unroll
                for (int pr = 0; pr < 4; ++pr) G[g][pr] = unpack2(acc[g][j][pr]);
#pragma unroll
            for (int n = 0; n < 8; ++n) {
                float Gi = ((n & 1) ? G[0][n >> 1].y : G[0][n >> 1].x)
                         + sm[OFF_CB2 + 0 * 64 + n0 + n];
                float Gf = ((n & 1) ? G[1][n >> 1].y : G[1][n >> 1].x)
                         + sm[OFF_CB2 + 1 * 64 + n0 + n];
                float Gg = ((n & 1) ? G[2][n >> 1].y : G[2][n >> 1].x)
                         + sm[OFF_CB2 + 2 * 64 + n0 + n];
                float Go = ((n & 1) ? G[3][n >> 1].y : G[3][n >> 1].x)
                         + sm[OFF_CB2 + 3 * 64 + n0 + n];
                float sp;
                cellpw(Gi, Gf, Gg, Go, syn2[n][j], mem2[n][j], sp, thr2);
                oa[j][0] += sp * sm[OFF_WOUT + wcol + n0 + n];
                oa[j][1] += sp * sm[OFF_WOUT + 1664 + wcol + n0 + n];
            }
        }
    }

    // ---- final mem2 contribution (columns 25*64 .. 25*64+63) ----
#pragma unroll
    for (int n = 0; n < 8; ++n) {
        float wm0 = sm[OFF_WOUT + 25 * 64 + n0 + n];
        float wm1 = sm[OFF_WOUT + 1664 + 25 * 64 + n0 + n];
#pragma unroll
        for (int j = 0; j < JB; ++j) {
            oa[j][0] += mem2[n][j] * wm0;
            oa[j][1] += mem2[n][j] * wm1;
        }
    }

    // ---- reduce over the 8 neuron-owner lanes of this group ----
#pragma unroll
    for (int j = 0; j < JB; ++j)
#pragma unroll
        for (int k = 0; k < 2; ++k) {
            float v = oa[j][k];
#pragma unroll
            for (int off = 4; off; off >>= 1)
                v += __shfl_xor_sync(FULLMASK, v, off);
            oa[j][k] = v;
        }

    if (p < 2 * JB) {
        int j = p >> 1, k = p & 1;
        out[(cta_b0 + bl + j) * 2 + k] = oa[j][k] + bout[k];
    }
}

extern "C" void kernel_launch(void* const* d_in, const int* in_sizes, int n_in,
                              void* d_out, int out_size) {
    const float* x    = (const float*)d_in[0];
    const float* Wih1 = (const float*)d_in[1];
    const float* Whh1 = (const float*)d_in[2];
    const float* bih1 = (const float*)d_in[3];
    const float* bhh1 = (const float*)d_in[4];
    const float* thr1 = (const float*)d_in[5];
    const float* Wih2 = (const float*)d_in[6];
    const float* Whh2 = (const float*)d_in[7];
    const float* bih2 = (const float*)d_in[8];
    const float* bhh2 = (const float*)d_in[9];
    const float* thr2 = (const float*)d_in[10];
    const float* Wout = (const float*)d_in[11];
    const float* bout = (const float*)d_in[12];
    float* out = (float*)d_out;

    int B = in_sizes[0] / 24;  // 65536

    cudaFuncSetAttribute(snn_kernel,
                         cudaFuncAttributeMaxDynamicSharedMemorySize,
                         SMEM_BYTES);

    snn_kernel<<<B / 64, NT, SMEM_BYTES>>>(
        x, Wih1, Whh1, bih1, bhh1, thr1,
        Wih2, Whh2, bih2, bhh2, thr2, Wout, bout, out);
}